// round 1
// baseline (speedup 1.0000x reference)
#include <cuda_runtime.h>
#include <math.h>

#define BB 8
#define SS 512
#define DD 256
#define NPAIRS (SS * (SS - 1) / 2)   // 130816
#define NTILES 36                     // 8*9/2 lower-tri 64x64 tiles per batch

// scratch for per-row squared norms (no cudaMalloc allowed)
__device__ float g_norms[BB * SS];

// ---------------------------------------------------------------------------
// Kernel 1: per-row squared L2 norms. One warp per row, float4 loads.
// ---------------------------------------------------------------------------
__global__ __launch_bounds__(256) void norms_kernel(const float* __restrict__ x) {
    int warp = (blockIdx.x * blockDim.x + threadIdx.x) >> 5;
    int lane = threadIdx.x & 31;
    if (warp >= BB * SS) return;
    const float4* x4 = reinterpret_cast<const float4*>(x) + (size_t)warp * (DD / 4);
    float4 a = x4[lane];
    float4 c = x4[lane + 32];
    float s = a.x * a.x + a.y * a.y + a.z * a.z + a.w * a.w
            + c.x * c.x + c.y * c.y + c.z * c.z + c.w * c.w;
#pragma unroll
    for (int o = 16; o; o >>= 1) s += __shfl_xor_sync(0xFFFFFFFFu, s, o);
    if (lane == 0) g_norms[warp] = s;
}

// ---------------------------------------------------------------------------
// Kernel 2: 64x64 pair tile per block, 4x4 micro-tile per thread.
// Shared memory is k-major [k][i] with XOR swizzle at float4 granularity:
// compute reads are conflict-free LDS.128.
// d^2(i,j) = n_i + n_j - 2*dot(x_i, x_j); out[b][i*(i-1)/2 + j] = sqrt(max(d2,eps))
// ---------------------------------------------------------------------------
__global__ __launch_bounds__(256) void dist_kernel(const float* __restrict__ x,
                                                   float* __restrict__ out) {
    __shared__ float4 As[64 * 16];  // [k][c] swizzled, 16KB
    __shared__ float4 Bs[64 * 16];

    int b = blockIdx.y;
    int t = blockIdx.x;  // 0..35 triangular tile index: t = ti*(ti+1)/2 + tj
    int ti = 0;
    while ((ti + 1) * (ti + 2) / 2 <= t) ti++;
    int tj = t - ti * (ti + 1) / 2;

    int tid = threadIdx.x;
    int tx = tid & 15;   // selects 4 i-rows
    int ty = tid >> 4;   // selects 4 j-rows

    const float* xb = x + (size_t)b * SS * DD;
    const float* xa_base = xb + (size_t)ti * 64 * DD;
    const float* xj_base = xb + (size_t)tj * 64 * DD;

    float* Asf = reinterpret_cast<float*>(As);
    float* Bsf = reinterpret_cast<float*>(Bs);

    float acc[4][4] = {};

    for (int k0 = 0; k0 < DD; k0 += 64) {
        // Load 64 rows x 64 k, transposed into smem. Each thread: 16 scalars/side.
        // Global reads coalesced along k; smem writes swizzled (bounded conflict).
#pragma unroll
        for (int it = 0; it < 16; ++it) {
            int e = it * 256 + tid;
            int kk = e & 63;
            int row = e >> 6;
            int c = row >> 2, sub = row & 3;
            int w = kk * 64 + ((c ^ (kk & 15)) << 2) + sub;
            Asf[w] = xa_base[row * DD + k0 + kk];
            Bsf[w] = xj_base[row * DD + k0 + kk];
        }
        __syncthreads();

#pragma unroll 16
        for (int k = 0; k < 64; ++k) {
            float4 av = As[k * 16 + (tx ^ (k & 15))];
            float4 bv = Bs[k * 16 + (ty ^ (k & 15))];
            acc[0][0] += av.x * bv.x; acc[0][1] += av.x * bv.y;
            acc[0][2] += av.x * bv.z; acc[0][3] += av.x * bv.w;
            acc[1][0] += av.y * bv.x; acc[1][1] += av.y * bv.y;
            acc[1][2] += av.y * bv.z; acc[1][3] += av.y * bv.w;
            acc[2][0] += av.z * bv.x; acc[2][1] += av.z * bv.y;
            acc[2][2] += av.z * bv.z; acc[2][3] += av.z * bv.w;
            acc[3][0] += av.w * bv.x; acc[3][1] += av.w * bv.y;
            acc[3][2] += av.w * bv.z; acc[3][3] += av.w * bv.w;
        }
        __syncthreads();
    }

    // Epilogue: combine with norms, write strict lower triangle.
    int i0 = ti * 64 + 4 * tx;
    int j0 = tj * 64 + 4 * ty;
    float ni[4], nj[4];
#pragma unroll
    for (int u = 0; u < 4; ++u) ni[u] = g_norms[b * SS + i0 + u];
#pragma unroll
    for (int v = 0; v < 4; ++v) nj[v] = g_norms[b * SS + j0 + v];

    float* ob = out + (size_t)b * NPAIRS;
#pragma unroll
    for (int u = 0; u < 4; ++u) {
        int i = i0 + u;
        int base = i * (i - 1) / 2;
#pragma unroll
        for (int v = 0; v < 4; ++v) {
            int j = j0 + v;
            if (j < i) {
                float d2 = ni[u] + nj[v] - 2.0f * acc[u][v];
                ob[base + j] = sqrtf(fmaxf(d2, 1e-7f));
            }
        }
    }
}

// ---------------------------------------------------------------------------
extern "C" void kernel_launch(void* const* d_in, const int* in_sizes, int n_in,
                              void* d_out, int out_size) {
    const float* x = (const float*)d_in[0];
    float* out = (float*)d_out;

    // 4096 rows, one warp each -> 512 blocks of 8 warps
    norms_kernel<<<512, 256>>>(x);

    dim3 grid(NTILES, BB);
    dist_kernel<<<grid, 256>>>(x, out);
}